// round 3
// baseline (speedup 1.0000x reference)
#include <cuda_runtime.h>
#include <cstdint>

#define HIDDEN   1024
#define EMB      512
#define KAUG     1536
#define NUM_OPS  8
#define BATCH    16384

#define BM 128
#define BN 128
#define BK 16
#define NTHREADS 256
#define AS_STRIDE (BM + 8)   // 136: 136 % 32 == 8 -> bank = 8*k + m (conflict-free patterns)
#define BS_STRIDE (BN + 8)

// ---- scratch (static device globals: no allocations allowed) ----
__device__ int   g_counts[NUM_OPS];
__device__ int   g_cursor[NUM_OPS];
__device__ int   g_offsets[NUM_OPS + 1];
__device__ int   g_perm[BATCH];
__device__ float g_h[(size_t)BATCH * HIDDEN];   // 64 MB intermediate, sorted order

// ---- routing kernels ----
__global__ void init_kernel() {
    int t = threadIdx.x;
    if (t < NUM_OPS) g_counts[t] = 0;
}

__global__ void hist_kernel(const int* __restrict__ ops) {
    int i = blockIdx.x * blockDim.x + threadIdx.x;
    if (i < BATCH) atomicAdd(&g_counts[ops[i]], 1);
}

__global__ void scan_kernel() {
    int acc = 0;
    for (int e = 0; e < NUM_OPS; ++e) {
        g_offsets[e] = acc;
        g_cursor[e]  = acc;
        acc += g_counts[e];
    }
    g_offsets[NUM_OPS] = acc;
}

__global__ void scatter_kernel(const int* __restrict__ ops) {
    int i = blockIdx.x * blockDim.x + threadIdx.x;
    if (i < BATCH) {
        int pos = atomicAdd(&g_cursor[ops[i]], 1);
        g_perm[pos] = i;   // slot order within an expert is atomic-race dependent,
                           // but per-token math (and thus output) is identical.
    }
}

// ---- tf32 helpers ----
__device__ __forceinline__ float to_tf32(float x) {
    float y;
    asm("cvt.rna.tf32.f32 %0, %1;" : "=f"(y) : "f"(x));
    return y;
}

__device__ __forceinline__ void mma_tf32(float c[4],
                                         uint32_t a0, uint32_t a1, uint32_t a2, uint32_t a3,
                                         uint32_t b0, uint32_t b1) {
    asm volatile(
        "mma.sync.aligned.m16n8k8.row.col.f32.tf32.tf32.f32 "
        "{%0,%1,%2,%3}, {%4,%5,%6,%7}, {%8,%9}, {%0,%1,%2,%3};"
        : "+f"(c[0]), "+f"(c[1]), "+f"(c[2]), "+f"(c[3])
        : "r"(a0), "r"(a1), "r"(a2), "r"(a3), "r"(b0), "r"(b1));
}

// ---- grouped GEMM ----
// LAYER 1: A = gather(x_aug) via g_perm (K=1536, cols >=1024 come from op_emb[e]),
//          Y = g_h (sorted rows), bias=b1, relu.
// LAYER 2: A = g_h rows (already sorted, K=1024),
//          Y = out[g_perm[row]], bias=b2, relu.
template <int LAYER>
__global__ __launch_bounds__(NTHREADS) void gemm_kernel(
    const float* __restrict__ X,      // x (layer1) / unused (layer2)
    const float* __restrict__ emb,    // op_emb (layer1) / unused
    const float* __restrict__ W,      // [NUM_OPS, K, HIDDEN]
    const float* __restrict__ bias,   // [NUM_OPS, HIDDEN]
    float* __restrict__ Y)            // unused (layer1) / out (layer2)
{
    const int e = blockIdx.z;
    const int seg_lo = g_offsets[e];
    const int seg_hi = g_offsets[e + 1];
    const int row0 = seg_lo + blockIdx.y * BM;
    if (row0 >= seg_hi) return;
    const int n0 = blockIdx.x * BN;
    const int K = (LAYER == 1) ? KAUG : HIDDEN;

    __shared__ float As[2][BK][AS_STRIDE];   // A transposed: As[k][m]
    __shared__ float Bs[2][BK][BS_STRIDE];   // Bs[k][n]

    const int tid  = threadIdx.x;
    const int lane = tid & 31;
    const int warp = tid >> 5;
    const int wm = (warp & 1) * 64;   // 2 warps along M
    const int wn = (warp >> 1) * 32;  // 4 warps along N

    // A loader: each thread owns row am, 2 float4 per slab
    const int am = tid & 127;
    const int ag = tid >> 7;          // 0/1
    int arow = row0 + am;
    if (arow > seg_hi - 1) arow = seg_hi - 1;   // clamp (result rows masked at store)
    const float* Arow;
    if (LAYER == 1) Arow = X + (size_t)g_perm[arow] * HIDDEN;
    else            Arow = g_h + (size_t)arow * HIDDEN;

    // B loader: warp reads one contiguous 512B k-row at a time
    const int bn4 = tid & 31;
    const int bkr = tid >> 5;         // 0..7
    const float* Wbase = W + (size_t)e * K * HIDDEN + n0 + 4 * bn4;

    float4 aReg[2], bReg[2];

    auto loadA = [&](int kbase) {
#pragma unroll
        for (int j = 0; j < 2; ++j) {
            int kk = kbase + 8 * ag + 4 * j;
            float4 v;
            if (LAYER == 1 && kk >= HIDDEN)
                v = *(const float4*)(emb + e * EMB + (kk - HIDDEN));
            else
                v = *(const float4*)(Arow + kk);
            v.x = to_tf32(v.x); v.y = to_tf32(v.y);
            v.z = to_tf32(v.z); v.w = to_tf32(v.w);
            aReg[j] = v;
        }
    };
    auto loadB = [&](int kbase) {
#pragma unroll
        for (int p = 0; p < 2; ++p) {
            int kk = kbase + bkr + 8 * p;
            float4 v = *(const float4*)(Wbase + (size_t)kk * HIDDEN);
            v.x = to_tf32(v.x); v.y = to_tf32(v.y);
            v.z = to_tf32(v.z); v.w = to_tf32(v.w);
            bReg[p] = v;
        }
    };
    auto storeA = [&](int buf) {
#pragma unroll
        for (int j = 0; j < 2; ++j) {
            int kl = 8 * ag + 4 * j;
            As[buf][kl + 0][am] = aReg[j].x;
            As[buf][kl + 1][am] = aReg[j].y;
            As[buf][kl + 2][am] = aReg[j].z;
            As[buf][kl + 3][am] = aReg[j].w;
        }
    };
    auto storeB = [&](int buf) {
#pragma unroll
        for (int p = 0; p < 2; ++p) {
            int kl = bkr + 8 * p;
            *(float4*)&Bs[buf][kl][4 * bn4] = bReg[p];
        }
    };

    float c[4][4][4];
#pragma unroll
    for (int mt = 0; mt < 4; ++mt)
#pragma unroll
        for (int nt = 0; nt < 4; ++nt)
#pragma unroll
            for (int i = 0; i < 4; ++i) c[mt][nt][i] = 0.f;

    const int r  = lane >> 2;
    const int cc = lane & 3;

    auto compute = [&](int buf) {
#pragma unroll
        for (int ks = 0; ks < 2; ++ks) {
            const int k8 = ks * 8;
            uint32_t af[4][4];
            uint32_t bf[4][2];
#pragma unroll
            for (int mt = 0; mt < 4; ++mt) {
                int m = wm + mt * 16 + r;
                af[mt][0] = __float_as_uint(As[buf][k8 + cc    ][m]);
                af[mt][1] = __float_as_uint(As[buf][k8 + cc    ][m + 8]);
                af[mt][2] = __float_as_uint(As[buf][k8 + cc + 4][m]);
                af[mt][3] = __float_as_uint(As[buf][k8 + cc + 4][m + 8]);
            }
#pragma unroll
            for (int nt = 0; nt < 4; ++nt) {
                int n = wn + nt * 8 + r;
                bf[nt][0] = __float_as_uint(Bs[buf][k8 + cc    ][n]);
                bf[nt][1] = __float_as_uint(Bs[buf][k8 + cc + 4][n]);
            }
#pragma unroll
            for (int mt = 0; mt < 4; ++mt)
#pragma unroll
                for (int nt = 0; nt < 4; ++nt)
                    mma_tf32(c[mt][nt], af[mt][0], af[mt][1], af[mt][2], af[mt][3],
                             bf[nt][0], bf[nt][1]);
        }
    };

    loadA(0); loadB(0);
    storeA(0); storeB(0);
    __syncthreads();

    const int KT = K / BK;
    for (int kt = 0; kt < KT; ++kt) {
        const int cur = kt & 1;
        if (kt + 1 < KT) { loadA((kt + 1) * BK); loadB((kt + 1) * BK); }
        compute(cur);
        if (kt + 1 < KT) { storeA(cur ^ 1); storeB(cur ^ 1); }
        __syncthreads();
    }

    // epilogue: bias + relu + (masked) store
    const float* brow = bias + e * HIDDEN;
#pragma unroll
    for (int mt = 0; mt < 4; ++mt) {
        const int rbase = row0 + wm + mt * 16 + r;
#pragma unroll
        for (int half = 0; half < 2; ++half) {
            const int row = rbase + half * 8;
            if (row >= seg_hi) continue;
            float* yrow;
            if (LAYER == 1) yrow = g_h + (size_t)row * HIDDEN;
            else            yrow = Y + (size_t)g_perm[row] * HIDDEN;
#pragma unroll
            for (int nt = 0; nt < 4; ++nt) {
                const int col = n0 + wn + nt * 8 + 2 * cc;
                float v0 = c[mt][nt][half * 2 + 0] + brow[col];
                float v1 = c[mt][nt][half * 2 + 1] + brow[col + 1];
                v0 = v0 > 0.f ? v0 : 0.f;
                v1 = v1 > 0.f ? v1 : 0.f;
                *(float2*)(yrow + col) = make_float2(v0, v1);
            }
        }
    }
}

extern "C" void kernel_launch(void* const* d_in, const int* in_sizes, int n_in,
                              void* d_out, int out_size) {
    const float* x      = (const float*)d_in[0];
    const int*   ops    = (const int*)  d_in[1];
    const float* op_emb = (const float*)d_in[2];
    const float* W1     = (const float*)d_in[3];
    const float* b1     = (const float*)d_in[4];
    const float* W2     = (const float*)d_in[5];
    const float* b2     = (const float*)d_in[6];
    float* out = (float*)d_out;

    init_kernel<<<1, 32>>>();
    hist_kernel<<<BATCH / 256, 256>>>(ops);
    scan_kernel<<<1, 1>>>();
    scatter_kernel<<<BATCH / 256, 256>>>(ops);

    dim3 grid(HIDDEN / BN, BATCH / BM, NUM_OPS);
    gemm_kernel<1><<<grid, NTHREADS>>>(x, op_emb, W1, b1, out /*unused*/);
    gemm_kernel<2><<<grid, NTHREADS>>>(nullptr, nullptr, W2, b2, out);
}